// round 7
// baseline (speedup 1.0000x reference)
#include <cuda_runtime.h>
#include <cstdint>

#define NPTS      1048576
#define TABLE_SZ  1048577
#define FEAT_DIM  8
#define NLEVELS   3

// One pass per octree level. 4 threads per point: lane h handles feats
// 2h..2h+1. A quad's four 8B gather loads land in the same 128B line ->
// 1 L1tex wavefront per corner entry, and each gather instruction carries
// only an 8-deep divergent replay chain (8 points/warp) instead of 16.
template <int LEVEL>
__global__ __launch_bounds__(256, 6) void octree_pass_kernel(
    const float* __restrict__ coord,     // (N, 3)
    const float* __restrict__ ftab,      // (TABLE, 8) for this level's table
    const int*   __restrict__ idx,       // (N, 8) for this level
    float*       __restrict__ out)       // (N, 8)
{
    const int t = blockIdx.x * blockDim.x + threadIdx.x;
    const int n = t >> 2;       // point id
    const int h = t & 3;        // feature pair (feats 2h, 2h+1)
    if (n >= NPTS) return;

    // Index loads first (all 4 lanes of a quad broadcast the same 32B).
    // Streamed (used once per pass) -> evict-first, keep L2 for the table.
    const int4* __restrict__ idxp = (const int4*)(idx + (size_t)n * 8);
    const int4 iA = __ldcs(idxp + 0);
    const int4 iB = __ldcs(idxp + 1);

    const float x = coord[3 * n + 0];
    const float y = coord[3 * n + 1];
    const float z = coord[3 * n + 2];

    // Issue all 8 gathers as early as possible; weight math overlaps latency.
    const int idx8[8] = {iA.x, iA.y, iA.z, iA.w, iB.x, iB.y, iB.z, iB.w};
    float2 g[8];
#pragma unroll
    for (int c = 0; c < 8; ++c) {
        g[c] = __ldg((const float2*)(ftab + (size_t)idx8[c] * FEAT_DIM) + h);
    }

    // current_level = 12 - LEVEL -> grid scale 2^(12-LEVEL)
    const float s = (float)(1 << (12 - LEVEL)) * 0.5f;
    float cx = fmaf(s, x, s);
    float cy = fmaf(s, y, s);
    float cz = fmaf(s, z, s);
    float tx = cx - floorf(cx);
    float ty = cy - floorf(cy);
    float tz = cz - floorf(cz);
    // smoothstep polynomial
    tx = tx * tx * (3.0f - 2.0f * tx);
    ty = ty * ty * (3.0f - 2.0f * ty);
    tz = tz * tz * (3.0f - 2.0f * tz);

    const float wx[2] = {1.0f - tx, tx};
    const float wy[2] = {1.0f - ty, ty};
    const float wz[2] = {1.0f - tz, tz};

    float a0 = 0.f, a1 = 0.f;
#pragma unroll
    for (int c = 0; c < 8; ++c) {
        float w = wx[(c >> 2) & 1] * wy[(c >> 1) & 1] * wz[c & 1];
        // reference zeroes the last table row
        if (idx8[c] == TABLE_SZ - 1) w = 0.0f;
        a0 = fmaf(w, g[c].x, a0);
        a1 = fmaf(w, g[c].y, a1);
    }

    float2* __restrict__ o = (float2*)(out + (size_t)n * FEAT_DIM) + h;
    if (LEVEL == 0) {
        __stcs(o, make_float2(a0, a1));
    } else {
        const float2 prev = __ldcs(o);
        __stcs(o, make_float2(prev.x + a0, prev.y + a1));
    }
}

extern "C" void kernel_launch(void* const* d_in, const int* in_sizes, int n_in,
                              void* d_out, int out_size)
{
    const float* coord    = (const float*)d_in[0];
    const float* features = (const float*)d_in[1];   // (3, TABLE, 8)
    const int*   indices  = (const int*)d_in[2];     // (3, N, 8)
    float*       out      = (float*)d_out;

    const size_t table_elems = (size_t)TABLE_SZ * FEAT_DIM;
    const size_t idx_elems   = (size_t)NPTS * 8;

    const int threads = 256;
    const int blocks = (4 * NPTS + threads - 1) / threads;

    // Pass i uses feature table (NLEVELS-1-i) and indices slice i.
    octree_pass_kernel<0><<<blocks, threads>>>(
        coord, features + 2 * table_elems, indices + 0 * idx_elems, out);
    octree_pass_kernel<1><<<blocks, threads>>>(
        coord, features + 1 * table_elems, indices + 1 * idx_elems, out);
    octree_pass_kernel<2><<<blocks, threads>>>(
        coord, features + 0 * table_elems, indices + 2 * idx_elems, out);
}

// round 9
// speedup vs baseline: 1.1233x; 1.1233x over previous
#include <cuda_runtime.h>
#include <cstdint>

#define NPTS      1048576
#define TABLE_SZ  1048577
#define FEAT_DIM  8
#define NLEVELS   3

// One pass per octree level. 2 threads per point: lane half h=0 handles
// feats 0-3, h=1 handles feats 4-7. The pair's two 16B gather loads hit the
// same 128B line -> 1 L1tex wavefront per corner entry.
// Gathers use .cg (no L1 allocate): random entries in a 32MB table never hit
// L1, so default loads just pay allocate/evict/fill-replay overhead and
// thrash the streaming lines.
template <int LEVEL>
__global__ __launch_bounds__(256) void octree_pass_kernel(
    const float* __restrict__ coord,     // (N, 3)
    const float* __restrict__ ftab,      // (TABLE, 8) for this level's table
    const int*   __restrict__ idx,       // (N, 8) for this level
    float*       __restrict__ out)       // (N, 8)
{
    const int t = blockIdx.x * blockDim.x + threadIdx.x;
    const int n = t >> 1;       // point id
    const int h = t & 1;        // feature half (0: feats 0-3, 1: feats 4-7)
    if (n >= NPTS) return;

    // Index loads first (both lanes of a pair broadcast the same 32B).
    const int4* __restrict__ idxp = (const int4*)(idx + (size_t)n * 8);
    const int4 iA = __ldg(idxp + 0);
    const int4 iB = __ldg(idxp + 1);

    const float x = coord[3 * n + 0];
    const float y = coord[3 * n + 1];
    const float z = coord[3 * n + 2];

    // Issue all 8 gathers as early as possible; weight math overlaps latency.
    const int idx8[8] = {iA.x, iA.y, iA.z, iA.w, iB.x, iB.y, iB.z, iB.w};
    float4 g[8];
#pragma unroll
    for (int c = 0; c < 8; ++c) {
        g[c] = __ldcg((const float4*)(ftab + (size_t)idx8[c] * FEAT_DIM) + h);
    }

    // current_level = 12 - LEVEL -> grid scale 2^(12-LEVEL)
    const float s = (float)(1 << (12 - LEVEL)) * 0.5f;
    float cx = fmaf(s, x, s);
    float cy = fmaf(s, y, s);
    float cz = fmaf(s, z, s);
    float tx = cx - floorf(cx);
    float ty = cy - floorf(cy);
    float tz = cz - floorf(cz);
    // smoothstep polynomial
    tx = tx * tx * (3.0f - 2.0f * tx);
    ty = ty * ty * (3.0f - 2.0f * ty);
    tz = tz * tz * (3.0f - 2.0f * tz);

    const float wx[2] = {1.0f - tx, tx};
    const float wy[2] = {1.0f - ty, ty};
    const float wz[2] = {1.0f - tz, tz};

    float a0 = 0.f, a1 = 0.f, a2 = 0.f, a3 = 0.f;
#pragma unroll
    for (int c = 0; c < 8; ++c) {
        float w = wx[(c >> 2) & 1] * wy[(c >> 1) & 1] * wz[c & 1];
        // reference zeroes the last table row
        if (idx8[c] == TABLE_SZ - 1) w = 0.0f;
        a0 = fmaf(w, g[c].x, a0);
        a1 = fmaf(w, g[c].y, a1);
        a2 = fmaf(w, g[c].z, a2);
        a3 = fmaf(w, g[c].w, a3);
    }

    float4* __restrict__ o = (float4*)(out + (size_t)n * FEAT_DIM) + h;
    if (LEVEL == 0) {
        *o = make_float4(a0, a1, a2, a3);
    } else {
        float4 prev = *o;
        *o = make_float4(prev.x + a0, prev.y + a1, prev.z + a2, prev.w + a3);
    }
}

extern "C" void kernel_launch(void* const* d_in, const int* in_sizes, int n_in,
                              void* d_out, int out_size)
{
    const float* coord    = (const float*)d_in[0];
    const float* features = (const float*)d_in[1];   // (3, TABLE, 8)
    const int*   indices  = (const int*)d_in[2];     // (3, N, 8)
    float*       out      = (float*)d_out;

    const size_t table_elems = (size_t)TABLE_SZ * FEAT_DIM;
    const size_t idx_elems   = (size_t)NPTS * 8;

    const int threads = 256;
    const int blocks = (2 * NPTS + threads - 1) / threads;

    // Pass i uses feature table (NLEVELS-1-i) and indices slice i.
    octree_pass_kernel<0><<<blocks, threads>>>(
        coord, features + 2 * table_elems, indices + 0 * idx_elems, out);
    octree_pass_kernel<1><<<blocks, threads>>>(
        coord, features + 1 * table_elems, indices + 1 * idx_elems, out);
    octree_pass_kernel<2><<<blocks, threads>>>(
        coord, features + 0 * table_elems, indices + 2 * idx_elems, out);
}